// round 4
// baseline (speedup 1.0000x reference)
#include <cuda_runtime.h>
#include <math.h>

#define BB   4
#define C8   8
#define C16  16
#define FF   256
#define TN   2000
#define CHW  (FF*TN)
#define TWO_PI_F     6.283185307179586f
#define INV_TWO_PI_F 0.15915494309189535f

typedef unsigned long long ull;

__device__ float g_s1[BB*2*C16*CHW];
__device__ float g_s2[BB*2*C16*CHW];

__device__ __forceinline__ float mod2pi(float a) {
    return a - floorf(a * INV_TWO_PI_F) * TWO_PI_F;
}

// ---- f32x2 packed helpers ----
__device__ __forceinline__ ull pk(float lo, float hi) {
    ull r; asm("mov.b64 %0,{%1,%2};" : "=l"(r) : "f"(lo), "f"(hi)); return r;
}
__device__ __forceinline__ void upk(ull v, float& lo, float& hi) {
    asm("mov.b64 {%0,%1},%2;" : "=f"(lo), "=f"(hi) : "l"(v));
}
__device__ __forceinline__ ull ffma2(ull a, ull b, ull c) {
    ull d; asm("fma.rn.f32x2 %0,%1,%2,%3;" : "=l"(d) : "l"(a), "l"(b), "l"(c)); return d;
}
__device__ __forceinline__ ull fmul2(ull a, ull b) {
    ull d; asm("mul.rn.f32x2 %0,%1,%2;" : "=l"(d) : "l"(a), "l"(b)); return d;
}
__device__ __forceinline__ ull ld64(const float* p) {
    return *reinterpret_cast<const ull*>(p);
}
__device__ __forceinline__ void st64(float* p, ull v) {
    *reinterpret_cast<ull*>(p) = v;
}

// ---------------------------------------------------------------------------
// Kernel A: cLog -> channel_shuffle (8->16) -> cAct.  2 timesteps per thread.
// ---------------------------------------------------------------------------
__global__ void kA(const float* __restrict__ x,
                   const float* __restrict__ wr, const float* __restrict__ wi,
                   const float* __restrict__ br, const float* __restrict__ bi)
{
    const int f = blockIdx.y;
    const int b = blockIdx.z;

    __shared__ ull swr2[C16*C8], swi2[C16*C8];
    __shared__ ull sbr2[C16], sbi2[C16];
    for (int i = threadIdx.x; i < C16*C8; i += blockDim.x) {
        float a = wr[f*C16*C8 + i]; swr2[i] = pk(a, a);
        float c = wi[f*C16*C8 + i]; swi2[i] = pk(c, c);
    }
    if (threadIdx.x < C16) {
        float a = br[f*C16 + threadIdx.x]; sbr2[threadIdx.x] = pk(a, a);
        float c = bi[f*C16 + threadIdx.x]; sbi2[threadIdx.x] = pk(c, c);
    }
    __syncthreads();

    const int tp = 2 * (blockIdx.x * blockDim.x + threadIdx.x);
    if (tp >= TN) return;
    const int off = f*TN + tp;

    ull lm2[C8], ph2[C8];
    #pragma unroll
    for (int c = 0; c < C8; c++) {
        ull xr = ld64(x + ((b*2+0)*C8 + c)*CHW + off);
        ull xi = ld64(x + ((b*2+1)*C8 + c)*CHW + off);
        float r0, r1, i0, i1;
        upk(xr, r0, r1); upk(xi, i0, i1);
        float l0 = 0.5f * __logf(fmaf(r0, r0, fmaf(i0, i0, 1e-12f)));
        float l1 = 0.5f * __logf(fmaf(r1, r1, fmaf(i1, i1, 1e-12f)));
        lm2[c] = pk(l0, l1);
        ph2[c] = pk(atan2f(i0, r0), atan2f(i1, r1));
    }
    #pragma unroll
    for (int o = 0; o < C16; o++) {
        ull sr = sbr2[o], si = sbi2[o];
        #pragma unroll
        for (int c = 0; c < C8; c++) {
            sr = ffma2(swr2[o*C8+c], lm2[c], sr);
            si = ffma2(swi2[o*C8+c], ph2[c], si);
        }
        float s0, s1, p0, p1;
        upk(sr, s0, s1); upk(si, p0, p1);
        float w0 = (__cosf(p0) + 1.0f) * 0.5f;
        float w1 = (__cosf(p1) + 1.0f) * 0.5f;
        st64(g_s1 + ((b*2+0)*C16 + o)*CHW + off, pk(w0*s0, w1*s1));
        st64(g_s1 + ((b*2+1)*C16 + o)*CHW + off, pk(mod2pi(p0), mod2pi(p1)));
    }
}

// ---------------------------------------------------------------------------
// Kernel B: freq_conv (depthwise over freq, k=5, pad=2) -> cAct. 2 t/thread.
// ---------------------------------------------------------------------------
__global__ void kB(const float* __restrict__ wr, const float* __restrict__ wi,
                   const float* __restrict__ br, const float* __restrict__ bi)
{
    const int f  = blockIdx.y;
    const int bc = blockIdx.z;
    const int b  = bc / C16;
    const int c  = bc % C16;
    const int tp = 2 * (blockIdx.x * blockDim.x + threadIdx.x);
    if (tp >= TN) return;

    const int base_r = ((b*2+0)*C16 + c)*CHW;
    const int base_i = ((b*2+1)*C16 + c)*CHW;

    float b_r = br[c], b_i = bi[c];
    ull yr = pk(b_r, b_r);
    ull yi = pk(b_i, b_i);
    #pragma unroll
    for (int j = 0; j < 5; j++) {
        int ff = f + j - 2;
        if (ff >= 0 && ff < FF) {
            float a = wr[c*5 + j]; float d = wi[c*5 + j];
            yr = ffma2(pk(a, a), ld64(g_s1 + base_r + ff*TN + tp), yr);
            yi = ffma2(pk(d, d), ld64(g_s1 + base_i + ff*TN + tp), yi);
        }
    }
    float r0, r1, i0, i1;
    upk(yr, r0, r1); upk(yi, i0, i1);
    float w0 = (__cosf(i0) + 1.0f) * 0.5f;
    float w1 = (__cosf(i1) + 1.0f) * 0.5f;
    st64(g_s2 + base_r + f*TN + tp, pk(w0*r0, w1*r1));
    st64(g_s2 + base_i + f*TN + tp, pk(mod2pi(i0), mod2pi(i1)));
}

// ---------------------------------------------------------------------------
// Kernel C: time_conv -> cExp -> ls(complex) -> cMul(x) -> la(complex) -> out
// 2 timesteps per thread; ALL matmul stages in packed f32x2.
// Weights pre-duplicated (w,w) in shared, contiguous over o -> LDS.128 pairs.
// ---------------------------------------------------------------------------
__global__ void __launch_bounds__(256) kC(
    const float* __restrict__ x,
    const float* __restrict__ twr, const float* __restrict__ twi,
    const float* __restrict__ tbr, const float* __restrict__ tbi,
    const float* __restrict__ lwr, const float* __restrict__ lwi,
    const float* __restrict__ lbr, const float* __restrict__ lbi,
    const float* __restrict__ awr, const float* __restrict__ awi,
    const float* __restrict__ abr, const float* __restrict__ abi,
    float* __restrict__ out)
{
    const int f = blockIdx.x & (FF-1);
    const int b = blockIdx.x >> 8;

    // tc weights: [(c*5+k)*8 + o] packed (w,w) -> 4x ulonglong2 per (c,k)
    __shared__ __align__(16) ull stw2r[C16*5*C8], stw2i[C16*5*C8];
    // ls/la weights: [o*8 + c] packed; nlw2i/naw2i are negated wi copies
    __shared__ __align__(16) ull slw2r[64], slw2i[64], nlw2i[64];
    __shared__ __align__(16) ull saw2r[64], saw2i[64], naw2i[64];
    __shared__ ull stb2r[8], stb2i[8];
    __shared__ ull slbd2[8], slbs2[8], sabd2[8], sabs2[8];

    for (int i = threadIdx.x; i < C16*5*C8; i += blockDim.x) {
        int o = i & 7, ck = i >> 3;
        int c = ck / 5, k = ck - 5*c;
        float a = twr[f*C8*C16*5 + (o*C16 + c)*5 + k];
        float d = twi[f*C8*C16*5 + (o*C16 + c)*5 + k];
        stw2r[i] = pk(a, a);
        stw2i[i] = pk(d, d);
    }
    if (threadIdx.x < 64) {
        float a = lwr[f*64 + threadIdx.x]; slw2r[threadIdx.x] = pk(a, a);
        float c = lwi[f*64 + threadIdx.x]; slw2i[threadIdx.x] = pk(c, c);
        nlw2i[threadIdx.x] = pk(-c, -c);
        float d = awr[f*64 + threadIdx.x]; saw2r[threadIdx.x] = pk(d, d);
        float e = awi[f*64 + threadIdx.x]; saw2i[threadIdx.x] = pk(e, e);
        naw2i[threadIdx.x] = pk(-e, -e);
    }
    if (threadIdx.x < 8) {
        float a = tbr[f*8 + threadIdx.x], c = tbi[f*8 + threadIdx.x];
        stb2r[threadIdx.x] = pk(a, a); stb2i[threadIdx.x] = pk(c, c);
        float d = lbr[f*8 + threadIdx.x], e = lbi[f*8 + threadIdx.x];
        slbd2[threadIdx.x] = pk(d - e, d - e); slbs2[threadIdx.x] = pk(d + e, d + e);
        float g = abr[f*8 + threadIdx.x], h = abi[f*8 + threadIdx.x];
        sabd2[threadIdx.x] = pk(g - h, g - h); sabs2[threadIdx.x] = pk(g + h, g + h);
    }
    __syncthreads();

    const float* s2r  = g_s2 + (b*2+0)*C16*CHW + f*TN;
    const float* s2i  = g_s2 + (b*2+1)*C16*CHW + f*TN;
    const float* xr_p = x    + (b*2+0)*C8 *CHW + f*TN;
    const float* xi_p = x    + (b*2+1)*C8 *CHW + f*TN;
    float* outr = out + (b*2+0)*C8*CHW + f*TN;
    float* outi = out + (b*2+1)*C8*CHW + f*TN;

    for (int t0 = 2*threadIdx.x; t0 < TN; t0 += 2*blockDim.x) {
        const bool full = (t0 + 9 < TN);

        // ---- time_conv: packed over the t-pair; taps ld64 are natural pairs ----
        ull ar2[8], ai2[8];
        #pragma unroll
        for (int o = 0; o < 8; o++) { ar2[o] = stb2r[o]; ai2[o] = stb2i[o]; }

        #pragma unroll
        for (int c = 0; c < C16; c++) {
            ull vr2[5], vi2[5];
            if (full) {
                #pragma unroll
                for (int k = 0; k < 5; k++) {
                    vr2[k] = ld64(s2r + c*CHW + t0 + 2*k);
                    vi2[k] = ld64(s2i + c*CHW + t0 + 2*k);
                }
            } else {
                #pragma unroll
                for (int k = 0; k < 5; k++) {
                    int ta = t0 + 2*k, tb2 = t0 + 1 + 2*k;
                    float r0 = (ta  < TN) ? s2r[c*CHW + ta ] : 0.0f;
                    float r1 = (tb2 < TN) ? s2r[c*CHW + tb2] : 0.0f;
                    float i0 = (ta  < TN) ? s2i[c*CHW + ta ] : 0.0f;
                    float i1 = (tb2 < TN) ? s2i[c*CHW + tb2] : 0.0f;
                    vr2[k] = pk(r0, r1);
                    vi2[k] = pk(i0, i1);
                }
            }
            #pragma unroll
            for (int k = 0; k < 5; k++) {
                const ulonglong2* wrp = reinterpret_cast<const ulonglong2*>(&stw2r[(c*5+k)*8]);
                const ulonglong2* wip = reinterpret_cast<const ulonglong2*>(&stw2i[(c*5+k)*8]);
                #pragma unroll
                for (int q = 0; q < 4; q++) {
                    ulonglong2 wr_ = wrp[q];
                    ulonglong2 wi_ = wip[q];
                    ar2[2*q  ] = ffma2(wr_.x, vr2[k], ar2[2*q  ]);
                    ar2[2*q+1] = ffma2(wr_.y, vr2[k], ar2[2*q+1]);
                    ai2[2*q  ] = ffma2(wi_.x, vi2[k], ai2[2*q  ]);
                    ai2[2*q+1] = ffma2(wi_.y, vi2[k], ai2[2*q+1]);
                }
            }
        }

        // ---- cExp (scalar MUFU per lane, reassembled into pairs) ----
        ull er2[8], ei2[8];
        #pragma unroll
        for (int o = 0; o < 8; o++) {
            float a0, a1, p0, p1;
            upk(ar2[o], a0, a1); upk(ai2[o], p0, p1);
            float r0 = __expf(a0), r1 = __expf(a1);
            float sn0, cs0, sn1, cs1;
            __sincosf(p0, &sn0, &cs0);
            __sincosf(p1, &sn1, &cs1);
            er2[o] = pk(r0*cs0, r1*cs1);
            ei2[o] = pk(r0*sn0, r1*sn1);
        }

        // ---- last_shuffle (complex 8x8, packed) ----
        ull sr2[8], si2[8];
        #pragma unroll
        for (int o = 0; o < 8; o++) {
            ull yr = slbd2[o], yi = slbs2[o];
            const ulonglong2* wr_p = reinterpret_cast<const ulonglong2*>(&slw2r[o*8]);
            const ulonglong2* wi_p = reinterpret_cast<const ulonglong2*>(&slw2i[o*8]);
            const ulonglong2* ni_p = reinterpret_cast<const ulonglong2*>(&nlw2i[o*8]);
            #pragma unroll
            for (int q = 0; q < 4; q++) {
                ulonglong2 wr_ = wr_p[q];
                ulonglong2 wi_ = wi_p[q];
                ulonglong2 ni_ = ni_p[q];
                yr = ffma2(wr_.x, er2[2*q  ], yr);
                yr = ffma2(ni_.x, ei2[2*q  ], yr);
                yi = ffma2(wr_.x, ei2[2*q  ], yi);
                yi = ffma2(wi_.x, er2[2*q  ], yi);
                yr = ffma2(wr_.y, er2[2*q+1], yr);
                yr = ffma2(ni_.y, ei2[2*q+1], yr);
                yi = ffma2(wr_.y, ei2[2*q+1], yi);
                yi = ffma2(wi_.y, er2[2*q+1], yi);
            }
            sr2[o] = yr; si2[o] = yi;
        }

        // ---- cMul with x (ld64 natural pairs) ----
        const ull NEG1 = 0xBF800000BF800000ull;  // (-1.0f, -1.0f)
        ull mr2[8], mi2[8];
        #pragma unroll
        for (int c = 0; c < 8; c++) {
            ull vxr = ld64(xr_p + c*CHW + t0);
            ull vxi = ld64(xi_p + c*CHW + t0);
            ull nsi = fmul2(si2[c], NEG1);
            mr2[c] = ffma2(sr2[c], vxr, fmul2(nsi, vxi));
            mi2[c] = ffma2(sr2[c], vxi, fmul2(si2[c], vxr));
        }

        // ---- last (complex 8x8, packed) -> out ----
        #pragma unroll
        for (int o = 0; o < 8; o++) {
            ull yr = sabd2[o], yi = sabs2[o];
            const ulonglong2* wr_p = reinterpret_cast<const ulonglong2*>(&saw2r[o*8]);
            const ulonglong2* wi_p = reinterpret_cast<const ulonglong2*>(&saw2i[o*8]);
            const ulonglong2* ni_p = reinterpret_cast<const ulonglong2*>(&naw2i[o*8]);
            #pragma unroll
            for (int q = 0; q < 4; q++) {
                ulonglong2 wr_ = wr_p[q];
                ulonglong2 wi_ = wi_p[q];
                ulonglong2 ni_ = ni_p[q];
                yr = ffma2(wr_.x, mr2[2*q  ], yr);
                yr = ffma2(ni_.x, mi2[2*q  ], yr);
                yi = ffma2(wr_.x, mi2[2*q  ], yi);
                yi = ffma2(wi_.x, mr2[2*q  ], yi);
                yr = ffma2(wr_.y, mr2[2*q+1], yr);
                yr = ffma2(ni_.y, mi2[2*q+1], yr);
                yi = ffma2(wr_.y, mi2[2*q+1], yi);
                yi = ffma2(wi_.y, mr2[2*q+1], yi);
            }
            st64(outr + o*CHW + t0, yr);
            st64(outi + o*CHW + t0, yi);
        }
    }
}

// ---------------------------------------------------------------------------
extern "C" void kernel_launch(void* const* d_in, const int* in_sizes, int n_in,
                              void* d_out, int out_size)
{
    const float* x     = (const float*)d_in[0];
    const float* cs_wr = (const float*)d_in[1];
    const float* cs_wi = (const float*)d_in[2];
    const float* cs_br = (const float*)d_in[3];
    const float* cs_bi = (const float*)d_in[4];
    const float* fc_wr = (const float*)d_in[5];
    const float* fc_wi = (const float*)d_in[6];
    const float* fc_br = (const float*)d_in[7];
    const float* fc_bi = (const float*)d_in[8];
    const float* tc_wr = (const float*)d_in[9];
    const float* tc_wi = (const float*)d_in[10];
    const float* tc_br = (const float*)d_in[11];
    const float* tc_bi = (const float*)d_in[12];
    const float* ls_wr = (const float*)d_in[13];
    const float* ls_wi = (const float*)d_in[14];
    const float* ls_br = (const float*)d_in[15];
    const float* ls_bi = (const float*)d_in[16];
    const float* la_wr = (const float*)d_in[17];
    const float* la_wi = (const float*)d_in[18];
    const float* la_br = (const float*)d_in[19];
    const float* la_bi = (const float*)d_in[20];
    float* out = (float*)d_out;

    dim3 gA((TN/2 + 255)/256, FF, BB);
    kA<<<gA, 256>>>(x, cs_wr, cs_wi, cs_br, cs_bi);

    dim3 gB((TN/2 + 255)/256, FF, BB*C16);
    kB<<<gB, 256>>>(fc_wr, fc_wi, fc_br, fc_bi);

    kC<<<BB*FF, 256>>>(x, tc_wr, tc_wi, tc_br, tc_bi,
                       ls_wr, ls_wi, ls_br, ls_bi,
                       la_wr, la_wi, la_br, la_bi, out);
}

// round 6
// speedup vs baseline: 1.0743x; 1.0743x over previous
#include <cuda_runtime.h>
#include <math.h>

#define BB   4
#define C8   8
#define C16  16
#define FF   256
#define TN   2000
#define CHW  (FF*TN)
#define TWO_PI_F     6.283185307179586f
#define INV_TWO_PI_F 0.15915494309189535f

// fused tile params
#define FT   16           // output freqs per block
#define FH   (FT+4)       // with halo
#define TC   32           // timesteps per block

__device__ float g_s2[BB*2*C16*CHW];

__device__ __forceinline__ float mod2pi(float a) {
    return a - floorf(a * INV_TWO_PI_F) * TWO_PI_F;
}

// ---------------------------------------------------------------------------
// Fused kernel AB: cLog -> channel_shuffle(8->16) -> cAct -> freq_conv(5, pad2)
//                  -> cAct -> g_s2
// block = (t_chunk, f_tile, b); 256 threads; dynamic smem.
// ---------------------------------------------------------------------------
#define SM_S1    0                       // FH*32*TC          = 20480 floats
#define SM_CSW   (FH*32*TC)              // FH*2*128          = 5120
#define SM_CSB   (SM_CSW + FH*2*128)     // FH*2*16           = 640
#define SM_FCW   (SM_CSB + FH*2*16)      // 2*80              = 160
#define SM_FCB   (SM_FCW + 160)          // 2*16              = 32
#define SM_TOTAL ((SM_FCB + 32) * 4)     // bytes = 105728

__global__ void __launch_bounds__(256) kAB(
    const float* __restrict__ x,
    const float* __restrict__ cswr, const float* __restrict__ cswi,
    const float* __restrict__ csbr, const float* __restrict__ csbi,
    const float* __restrict__ fcwr, const float* __restrict__ fcwi,
    const float* __restrict__ fcbr, const float* __restrict__ fcbi)
{
    extern __shared__ float sm[];
    float* s1  = sm + SM_S1;    // [(fl*32 + ri*16 + ch)*TC + tl]
    float* csw = sm + SM_CSW;   // [(fl*2 + ri)*128 + o*8 + c]
    float* csb = sm + SM_CSB;   // [(fl*2 + ri)*16 + o]
    float* fcw = sm + SM_FCW;   // [ri*80 + c*5 + j]
    float* fcb = sm + SM_FCB;   // [ri*16 + c]

    const int b     = blockIdx.z;
    const int fTile = blockIdx.y;
    const int t0    = blockIdx.x * TC;
    const int tid   = threadIdx.x;

    // ---- stage weights ----
    for (int i = tid; i < FH*2*128; i += 256) {
        int fl = i >> 8, rest = i & 255;
        int ri = rest >> 7, idx = rest & 127;
        int fg = fTile*FT + fl - 2;
        float v = 0.0f;
        if (fg >= 0 && fg < FF)
            v = (ri ? cswi : cswr)[fg*128 + idx];
        csw[(fl*2 + ri)*128 + idx] = v;
    }
    for (int i = tid; i < FH*2*16; i += 256) {
        int fl = i >> 5, rest = i & 31;
        int ri = rest >> 4, o = rest & 15;
        int fg = fTile*FT + fl - 2;
        float v = 0.0f;
        if (fg >= 0 && fg < FF)
            v = (ri ? csbi : csbr)[fg*16 + o];
        csb[(fl*2 + ri)*16 + o] = v;
    }
    if (tid < 80) {                 // fc_wr / fc_wi are 16*5 = 80 elements each
        fcw[tid]      = fcwr[tid];
        fcw[80 + tid] = fcwi[tid];
    } else if (tid < 96) {
        int c = tid - 80;
        fcb[c]      = fcbr[c];
        fcb[16 + c] = fcbi[c];
    }
    __syncthreads();

    // ---- phase 1: kA into s1 tile (halo freqs included) ----
    for (int idx = tid; idx < FH*TC; idx += 256) {
        const int fl = idx >> 5, tl = idx & 31;
        const int fg = fTile*FT + fl - 2;
        const int tg = t0 + tl;
        if (fg < 0 || fg >= FF || tg >= TN) {
            #pragma unroll
            for (int ch2 = 0; ch2 < 32; ch2++)
                s1[(fl*32 + ch2)*TC + tl] = 0.0f;
            continue;
        }
        const int off = fg*TN + tg;
        float lm[C8], ph[C8];
        #pragma unroll
        for (int c = 0; c < C8; c++) {
            float xr = x[((b*2+0)*C8 + c)*CHW + off];
            float xi = x[((b*2+1)*C8 + c)*CHW + off];
            lm[c] = 0.5f * __logf(fmaf(xr, xr, fmaf(xi, xi, 1e-12f)));
            ph[c] = atan2f(xi, xr);
        }
        const float* wr_ = csw + (fl*2+0)*128;
        const float* wi_ = csw + (fl*2+1)*128;
        const float* br_ = csb + (fl*2+0)*16;
        const float* bi_ = csb + (fl*2+1)*16;
        #pragma unroll
        for (int o = 0; o < C16; o++) {
            float sr = br_[o], si = bi_[o];
            #pragma unroll
            for (int c = 0; c < C8; c++) {
                sr = fmaf(wr_[o*8+c], lm[c], sr);
                si = fmaf(wi_[o*8+c], ph[c], si);
            }
            float w = (__cosf(si) + 1.0f) * 0.5f;
            s1[(fl*32 + o)*TC + tl]      = w * sr;
            s1[(fl*32 + 16 + o)*TC + tl] = mod2pi(si);
        }
    }
    __syncthreads();

    // ---- phase 2: kB from s1 tile -> g_s2 ----
    for (int idx = tid; idx < FT*C16*TC; idx += 256) {   // 16*16*32 = 8192
        const int tl = idx & 31;
        const int c  = (idx >> 5) & 15;
        const int flo = idx >> 9;          // 0..15
        const int tg = t0 + tl;
        if (tg >= TN) continue;
        const int fg = fTile*FT + flo;

        float yr = fcb[c], yi = fcb[16 + c];
        #pragma unroll
        for (int j = 0; j < 5; j++) {
            const int fl = flo + j;        // local halo index for global f + j - 2
            yr = fmaf(fcw[c*5 + j],      s1[(fl*32 + c)*TC + tl],      yr);
            yi = fmaf(fcw[80 + c*5 + j], s1[(fl*32 + 16 + c)*TC + tl], yi);
        }
        float w = (__cosf(yi) + 1.0f) * 0.5f;
        g_s2[((b*2+0)*C16 + c)*CHW + fg*TN + tg] = w * yr;
        g_s2[((b*2+1)*C16 + c)*CHW + fg*TN + tg] = mod2pi(yi);
    }
}

// ---------------------------------------------------------------------------
// Kernel C (R3 version): time_conv -> cExp -> ls(complex) -> cMul(x)
//                        -> la(complex) -> out.  2 t/thread, scalar FFMA.
// ---------------------------------------------------------------------------
template<bool FULL>
__device__ __forceinline__ void tc_core(
    const float* __restrict__ s2r, const float* __restrict__ s2i,
    const float* __restrict__ stwr, const float* __restrict__ stwi,
    int t0, float ar[8][2], float ai[8][2])
{
    #pragma unroll
    for (int c = 0; c < C16; c++) {
        float vr[10], vi[10];
        if (FULL) {
            #pragma unroll
            for (int m = 0; m < 5; m++) {
                float2 a = *reinterpret_cast<const float2*>(s2r + c*CHW + t0 + 2*m);
                float2 d = *reinterpret_cast<const float2*>(s2i + c*CHW + t0 + 2*m);
                vr[2*m] = a.x; vr[2*m+1] = a.y;
                vi[2*m] = d.x; vi[2*m+1] = d.y;
            }
        } else {
            #pragma unroll
            for (int j = 0; j < 10; j++) {
                int tt = t0 + j;
                vr[j] = (tt < TN) ? s2r[c*CHW + tt] : 0.0f;
                vi[j] = (tt < TN) ? s2i[c*CHW + tt] : 0.0f;
            }
        }
        #pragma unroll
        for (int k = 0; k < 5; k++) {
            const float4 wr0 = *reinterpret_cast<const float4*>(stwr + (c*5+k)*8);
            const float4 wr1 = *reinterpret_cast<const float4*>(stwr + (c*5+k)*8 + 4);
            const float4 wi0 = *reinterpret_cast<const float4*>(stwi + (c*5+k)*8);
            const float4 wi1 = *reinterpret_cast<const float4*>(stwi + (c*5+k)*8 + 4);
            const float wrs[8] = {wr0.x, wr0.y, wr0.z, wr0.w, wr1.x, wr1.y, wr1.z, wr1.w};
            const float wis[8] = {wi0.x, wi0.y, wi0.z, wi0.w, wi1.x, wi1.y, wi1.z, wi1.w};
            #pragma unroll
            for (int o = 0; o < 8; o++) {
                ar[o][0] = fmaf(wrs[o], vr[2*k],   ar[o][0]);
                ar[o][1] = fmaf(wrs[o], vr[2*k+1], ar[o][1]);
                ai[o][0] = fmaf(wis[o], vi[2*k],   ai[o][0]);
                ai[o][1] = fmaf(wis[o], vi[2*k+1], ai[o][1]);
            }
        }
    }
}

__global__ void __launch_bounds__(256) kC(
    const float* __restrict__ x,
    const float* __restrict__ twr, const float* __restrict__ twi,
    const float* __restrict__ tbr, const float* __restrict__ tbi,
    const float* __restrict__ lwr, const float* __restrict__ lwi,
    const float* __restrict__ lbr, const float* __restrict__ lbi,
    const float* __restrict__ awr, const float* __restrict__ awi,
    const float* __restrict__ abr, const float* __restrict__ abi,
    float* __restrict__ out)
{
    const int f = blockIdx.x & (FF-1);
    const int b = blockIdx.x >> 8;

    __shared__ __align__(16) float stwr[C8*C16*5], stwi[C8*C16*5];  // [(c*5+k)*8+o]
    __shared__ float slwr[64], slwi[64], sawr[64], sawi[64];        // [o*8+c]
    __shared__ float stbr[8], stbi[8], slbr[8], slbi[8], sabr[8], sabi[8];

    for (int i = threadIdx.x; i < C8*C16*5; i += blockDim.x) {
        int o = i & 7, ck = i >> 3;
        int c = ck / 5, k = ck - 5*c;
        stwr[i] = twr[f*C8*C16*5 + (o*C16 + c)*5 + k];
        stwi[i] = twi[f*C8*C16*5 + (o*C16 + c)*5 + k];
    }
    if (threadIdx.x < 64) {
        slwr[threadIdx.x] = lwr[f*64 + threadIdx.x];
        slwi[threadIdx.x] = lwi[f*64 + threadIdx.x];
        sawr[threadIdx.x] = awr[f*64 + threadIdx.x];
        sawi[threadIdx.x] = awi[f*64 + threadIdx.x];
    }
    if (threadIdx.x < 8) {
        stbr[threadIdx.x] = tbr[f*8 + threadIdx.x];
        stbi[threadIdx.x] = tbi[f*8 + threadIdx.x];
        slbr[threadIdx.x] = lbr[f*8 + threadIdx.x];
        slbi[threadIdx.x] = lbi[f*8 + threadIdx.x];
        sabr[threadIdx.x] = abr[f*8 + threadIdx.x];
        sabi[threadIdx.x] = abi[f*8 + threadIdx.x];
    }
    __syncthreads();

    const float* s2r  = g_s2 + (b*2+0)*C16*CHW + f*TN;
    const float* s2i  = g_s2 + (b*2+1)*C16*CHW + f*TN;
    const float* xr_p = x    + (b*2+0)*C8 *CHW + f*TN;
    const float* xi_p = x    + (b*2+1)*C8 *CHW + f*TN;
    float* outr = out + (b*2+0)*C8*CHW + f*TN;
    float* outi = out + (b*2+1)*C8*CHW + f*TN;

    for (int t0 = 2*threadIdx.x; t0 < TN; t0 += 2*blockDim.x) {
        float ar[8][2], ai[8][2];
        #pragma unroll
        for (int o = 0; o < 8; o++) {
            ar[o][0] = stbr[o]; ar[o][1] = stbr[o];
            ai[o][0] = stbi[o]; ai[o][1] = stbi[o];
        }

        if (t0 + 9 < TN) tc_core<true >(s2r, s2i, stwr, stwi, t0, ar, ai);
        else             tc_core<false>(s2r, s2i, stwr, stwi, t0, ar, ai);

        float orj[8][2], oij[8][2];
        #pragma unroll
        for (int j = 0; j < 2; j++) {
            float er[8], ei[8];
            #pragma unroll
            for (int o = 0; o < 8; o++) {
                float r = __expf(ar[o][j]);
                float sn, cs;
                __sincosf(ai[o][j], &sn, &cs);
                er[o] = r * cs;
                ei[o] = r * sn;
            }
            float sr[8], si[8];
            #pragma unroll
            for (int o = 0; o < 8; o++) {
                float yr = slbr[o] - slbi[o];
                float yi = slbr[o] + slbi[o];
                #pragma unroll
                for (int c = 0; c < 8; c++) {
                    float wr_ = slwr[o*8+c], wi_ = slwi[o*8+c];
                    yr = fmaf(wr_, er[c], yr);
                    yr = fmaf(-wi_, ei[c], yr);
                    yi = fmaf(wr_, ei[c], yi);
                    yi = fmaf(wi_, er[c], yi);
                }
                sr[o] = yr; si[o] = yi;
            }
            float mr[8], mi[8];
            #pragma unroll
            for (int c = 0; c < 8; c++) {
                float vxr = xr_p[c*CHW + t0 + j];
                float vxi = xi_p[c*CHW + t0 + j];
                mr[c] = sr[c]*vxr - si[c]*vxi;
                mi[c] = sr[c]*vxi + si[c]*vxr;
            }
            #pragma unroll
            for (int o = 0; o < 8; o++) {
                float yr = sabr[o] - sabi[o];
                float yi = sabr[o] + sabi[o];
                #pragma unroll
                for (int c = 0; c < 8; c++) {
                    float wr_ = sawr[o*8+c], wi_ = sawi[o*8+c];
                    yr = fmaf(wr_, mr[c], yr);
                    yr = fmaf(-wi_, mi[c], yr);
                    yi = fmaf(wr_, mi[c], yi);
                    yi = fmaf(wi_, mr[c], yi);
                }
                orj[o][j] = yr; oij[o][j] = yi;
            }
        }
        #pragma unroll
        for (int o = 0; o < 8; o++) {
            *reinterpret_cast<float2*>(outr + o*CHW + t0) = make_float2(orj[o][0], orj[o][1]);
            *reinterpret_cast<float2*>(outi + o*CHW + t0) = make_float2(oij[o][0], oij[o][1]);
        }
    }
}

// ---------------------------------------------------------------------------
extern "C" void kernel_launch(void* const* d_in, const int* in_sizes, int n_in,
                              void* d_out, int out_size)
{
    const float* x     = (const float*)d_in[0];
    const float* cs_wr = (const float*)d_in[1];
    const float* cs_wi = (const float*)d_in[2];
    const float* cs_br = (const float*)d_in[3];
    const float* cs_bi = (const float*)d_in[4];
    const float* fc_wr = (const float*)d_in[5];
    const float* fc_wi = (const float*)d_in[6];
    const float* fc_br = (const float*)d_in[7];
    const float* fc_bi = (const float*)d_in[8];
    const float* tc_wr = (const float*)d_in[9];
    const float* tc_wi = (const float*)d_in[10];
    const float* tc_br = (const float*)d_in[11];
    const float* tc_bi = (const float*)d_in[12];
    const float* ls_wr = (const float*)d_in[13];
    const float* ls_wi = (const float*)d_in[14];
    const float* ls_br = (const float*)d_in[15];
    const float* ls_bi = (const float*)d_in[16];
    const float* la_wr = (const float*)d_in[17];
    const float* la_wi = (const float*)d_in[18];
    const float* la_br = (const float*)d_in[19];
    const float* la_bi = (const float*)d_in[20];
    float* out = (float*)d_out;

    cudaFuncSetAttribute(kAB, cudaFuncAttributeMaxDynamicSharedMemorySize, SM_TOTAL);

    dim3 gAB((TN + TC - 1)/TC, FF/FT, BB);   // 63, 16, 4
    kAB<<<gAB, 256, SM_TOTAL>>>(x, cs_wr, cs_wi, cs_br, cs_bi,
                                fc_wr, fc_wi, fc_br, fc_bi);

    kC<<<BB*FF, 256>>>(x, tc_wr, tc_wi, tc_br, tc_bi,
                       ls_wr, ls_wi, ls_br, ls_bi,
                       la_wr, la_wi, la_br, la_bi, out);
}

// round 7
// speedup vs baseline: 1.1263x; 1.0484x over previous
#include <cuda_runtime.h>
#include <math.h>

#define BB   4
#define C8   8
#define C16  16
#define FF   256
#define TN   2000
#define CHW  (FF*TN)
#define TWO_PI_F     6.283185307179586f
#define INV_TWO_PI_F 0.15915494309189535f

typedef unsigned long long ull;

__device__ float g_s1[BB*2*C16*CHW];
__device__ float g_s2[BB*2*C16*CHW];

__device__ __forceinline__ float mod2pi(float a) {
    return a - floorf(a * INV_TWO_PI_F) * TWO_PI_F;
}

// ---- f32x2 helpers (kA/kB only) ----
__device__ __forceinline__ ull pk(float lo, float hi) {
    ull r; asm("mov.b64 %0,{%1,%2};" : "=l"(r) : "f"(lo), "f"(hi)); return r;
}
__device__ __forceinline__ void upk(ull v, float& lo, float& hi) {
    asm("mov.b64 {%0,%1},%2;" : "=f"(lo), "=f"(hi) : "l"(v));
}
__device__ __forceinline__ ull ffma2(ull a, ull b, ull c) {
    ull d; asm("fma.rn.f32x2 %0,%1,%2,%3;" : "=l"(d) : "l"(a), "l"(b), "l"(c)); return d;
}
__device__ __forceinline__ ull ld64(const float* p) {
    return *reinterpret_cast<const ull*>(p);
}
__device__ __forceinline__ void st64(float* p, ull v) {
    *reinterpret_cast<ull*>(p) = v;
}

// ---------------------------------------------------------------------------
// Kernel A: cLog -> channel_shuffle (8->16) -> cAct.  2 timesteps per thread.
// (measured 106 us)
// ---------------------------------------------------------------------------
__global__ void kA(const float* __restrict__ x,
                   const float* __restrict__ wr, const float* __restrict__ wi,
                   const float* __restrict__ br, const float* __restrict__ bi)
{
    const int f = blockIdx.y;
    const int b = blockIdx.z;

    __shared__ ull swr2[C16*C8], swi2[C16*C8];
    __shared__ ull sbr2[C16], sbi2[C16];
    for (int i = threadIdx.x; i < C16*C8; i += blockDim.x) {
        float a = wr[f*C16*C8 + i]; swr2[i] = pk(a, a);
        float c = wi[f*C16*C8 + i]; swi2[i] = pk(c, c);
    }
    if (threadIdx.x < C16) {
        float a = br[f*C16 + threadIdx.x]; sbr2[threadIdx.x] = pk(a, a);
        float c = bi[f*C16 + threadIdx.x]; sbi2[threadIdx.x] = pk(c, c);
    }
    __syncthreads();

    const int tp = 2 * (blockIdx.x * blockDim.x + threadIdx.x);
    if (tp >= TN) return;
    const int off = f*TN + tp;

    ull lm2[C8], ph2[C8];
    #pragma unroll
    for (int c = 0; c < C8; c++) {
        ull xr = ld64(x + ((b*2+0)*C8 + c)*CHW + off);
        ull xi = ld64(x + ((b*2+1)*C8 + c)*CHW + off);
        float r0, r1, i0, i1;
        upk(xr, r0, r1); upk(xi, i0, i1);
        float l0 = 0.5f * __logf(fmaf(r0, r0, fmaf(i0, i0, 1e-12f)));
        float l1 = 0.5f * __logf(fmaf(r1, r1, fmaf(i1, i1, 1e-12f)));
        lm2[c] = pk(l0, l1);
        ph2[c] = pk(atan2f(i0, r0), atan2f(i1, r1));
    }
    #pragma unroll
    for (int o = 0; o < C16; o++) {
        ull sr = sbr2[o], si = sbi2[o];
        #pragma unroll
        for (int c = 0; c < C8; c++) {
            sr = ffma2(swr2[o*C8+c], lm2[c], sr);
            si = ffma2(swi2[o*C8+c], ph2[c], si);
        }
        float s0, s1, p0, p1;
        upk(sr, s0, s1); upk(si, p0, p1);
        float w0 = (__cosf(p0) + 1.0f) * 0.5f;
        float w1 = (__cosf(p1) + 1.0f) * 0.5f;
        st64(g_s1 + ((b*2+0)*C16 + o)*CHW + off, pk(w0*s0, w1*s1));
        st64(g_s1 + ((b*2+1)*C16 + o)*CHW + off, pk(mod2pi(p0), mod2pi(p1)));
    }
}

// ---------------------------------------------------------------------------
// Kernel B: freq_conv (depthwise over freq, k=5, pad=2) -> cAct. 2 t/thread.
// ---------------------------------------------------------------------------
__global__ void kB(const float* __restrict__ wr, const float* __restrict__ wi,
                   const float* __restrict__ br, const float* __restrict__ bi)
{
    const int f  = blockIdx.y;
    const int bc = blockIdx.z;
    const int b  = bc / C16;
    const int c  = bc % C16;
    const int tp = 2 * (blockIdx.x * blockDim.x + threadIdx.x);
    if (tp >= TN) return;

    const int base_r = ((b*2+0)*C16 + c)*CHW;
    const int base_i = ((b*2+1)*C16 + c)*CHW;

    float b_r = br[c], b_i = bi[c];
    ull yr = pk(b_r, b_r);
    ull yi = pk(b_i, b_i);
    #pragma unroll
    for (int j = 0; j < 5; j++) {
        int ff = f + j - 2;
        if (ff >= 0 && ff < FF) {
            float a = wr[c*5 + j]; float d = wi[c*5 + j];
            yr = ffma2(pk(a, a), ld64(g_s1 + base_r + ff*TN + tp), yr);
            yi = ffma2(pk(d, d), ld64(g_s1 + base_i + ff*TN + tp), yi);
        }
    }
    float r0, r1, i0, i1;
    upk(yr, r0, r1); upk(yi, i0, i1);
    float w0 = (__cosf(i0) + 1.0f) * 0.5f;
    float w1 = (__cosf(i1) + 1.0f) * 0.5f;
    st64(g_s2 + base_r + f*TN + tp, pk(w0*r0, w1*r1));
    st64(g_s2 + base_i + f*TN + tp, pk(mod2pi(i0), mod2pi(i1)));
}

// ---------------------------------------------------------------------------
// Kernel C: 1 timestep/thread, register-lean, 2 blocks/SM target.
// time_conv(16->8, taps t+2k) -> cExp -> ls(cplx) -> cMul(x) -> la(cplx) -> out
// ---------------------------------------------------------------------------
__global__ void __launch_bounds__(256, 2) kC(
    const float* __restrict__ x,
    const float* __restrict__ twr, const float* __restrict__ twi,
    const float* __restrict__ tbr, const float* __restrict__ tbi,
    const float* __restrict__ lwr, const float* __restrict__ lwi,
    const float* __restrict__ lbr, const float* __restrict__ lbi,
    const float* __restrict__ awr, const float* __restrict__ awi,
    const float* __restrict__ abr, const float* __restrict__ abi,
    float* __restrict__ out)
{
    const int f = blockIdx.x & (FF-1);
    const int b = blockIdx.x >> 8;

    __shared__ __align__(16) float stwr[C8*C16*5], stwi[C8*C16*5];  // [(c*5+k)*8+o]
    __shared__ float slwr[64], slwi[64], sawr[64], sawi[64];        // [o*8+c]
    __shared__ float stbr[8], stbi[8], slbr[8], slbi[8], sabr[8], sabi[8];

    for (int i = threadIdx.x; i < C8*C16*5; i += blockDim.x) {
        int o = i & 7, ck = i >> 3;
        int c = ck / 5, k = ck - 5*c;
        stwr[i] = twr[f*C8*C16*5 + (o*C16 + c)*5 + k];
        stwi[i] = twi[f*C8*C16*5 + (o*C16 + c)*5 + k];
    }
    if (threadIdx.x < 64) {
        slwr[threadIdx.x] = lwr[f*64 + threadIdx.x];
        slwi[threadIdx.x] = lwi[f*64 + threadIdx.x];
        sawr[threadIdx.x] = awr[f*64 + threadIdx.x];
        sawi[threadIdx.x] = awi[f*64 + threadIdx.x];
    }
    if (threadIdx.x < 8) {
        stbr[threadIdx.x] = tbr[f*8 + threadIdx.x];
        stbi[threadIdx.x] = tbi[f*8 + threadIdx.x];
        slbr[threadIdx.x] = lbr[f*8 + threadIdx.x];
        slbi[threadIdx.x] = lbi[f*8 + threadIdx.x];
        sabr[threadIdx.x] = abr[f*8 + threadIdx.x];
        sabi[threadIdx.x] = abi[f*8 + threadIdx.x];
    }
    __syncthreads();

    const float* s2r  = g_s2 + (b*2+0)*C16*CHW + f*TN;
    const float* s2i  = g_s2 + (b*2+1)*C16*CHW + f*TN;
    const float* xr_p = x    + (b*2+0)*C8 *CHW + f*TN;
    const float* xi_p = x    + (b*2+1)*C8 *CHW + f*TN;
    float* outr = out + (b*2+0)*C8*CHW + f*TN;
    float* outi = out + (b*2+1)*C8*CHW + f*TN;

    for (int t = threadIdx.x; t < TN; t += 256) {
        const bool full = (t + 9 < TN);

        // ---- time_conv: 8 real + 8 imag accumulators ----
        float ar[8], ai[8];
        #pragma unroll
        for (int o = 0; o < 8; o++) { ar[o] = stbr[o]; ai[o] = stbi[o]; }

        #pragma unroll
        for (int c = 0; c < C16; c++) {
            float vr[5], vi[5];
            if (full) {
                #pragma unroll
                for (int k = 0; k < 5; k++) {
                    vr[k] = s2r[c*CHW + t + 2*k];
                    vi[k] = s2i[c*CHW + t + 2*k];
                }
            } else {
                #pragma unroll
                for (int k = 0; k < 5; k++) {
                    int tt = t + 2*k;
                    vr[k] = (tt < TN) ? s2r[c*CHW + tt] : 0.0f;
                    vi[k] = (tt < TN) ? s2i[c*CHW + tt] : 0.0f;
                }
            }
            #pragma unroll
            for (int k = 0; k < 5; k++) {
                const float4 wr0 = *reinterpret_cast<const float4*>(stwr + (c*5+k)*8);
                const float4 wr1 = *reinterpret_cast<const float4*>(stwr + (c*5+k)*8 + 4);
                const float4 wi0 = *reinterpret_cast<const float4*>(stwi + (c*5+k)*8);
                const float4 wi1 = *reinterpret_cast<const float4*>(stwi + (c*5+k)*8 + 4);
                ar[0] = fmaf(wr0.x, vr[k], ar[0]);
                ar[1] = fmaf(wr0.y, vr[k], ar[1]);
                ar[2] = fmaf(wr0.z, vr[k], ar[2]);
                ar[3] = fmaf(wr0.w, vr[k], ar[3]);
                ar[4] = fmaf(wr1.x, vr[k], ar[4]);
                ar[5] = fmaf(wr1.y, vr[k], ar[5]);
                ar[6] = fmaf(wr1.z, vr[k], ar[6]);
                ar[7] = fmaf(wr1.w, vr[k], ar[7]);
                ai[0] = fmaf(wi0.x, vi[k], ai[0]);
                ai[1] = fmaf(wi0.y, vi[k], ai[1]);
                ai[2] = fmaf(wi0.z, vi[k], ai[2]);
                ai[3] = fmaf(wi0.w, vi[k], ai[3]);
                ai[4] = fmaf(wi1.x, vi[k], ai[4]);
                ai[5] = fmaf(wi1.y, vi[k], ai[5]);
                ai[6] = fmaf(wi1.z, vi[k], ai[6]);
                ai[7] = fmaf(wi1.w, vi[k], ai[7]);
            }
        }

        // ---- cExp (overwrite ar/ai with er/ei to keep live set small) ----
        #pragma unroll
        for (int o = 0; o < 8; o++) {
            float r = __expf(ar[o]);
            float sn, cs;
            __sincosf(ai[o], &sn, &cs);
            ar[o] = r * cs;   // er
            ai[o] = r * sn;   // ei
        }

        // ---- last_shuffle (complex 8x8) ----
        float sr[8], si[8];
        #pragma unroll
        for (int o = 0; o < 8; o++) {
            float yr = slbr[o] - slbi[o];
            float yi = slbr[o] + slbi[o];
            #pragma unroll
            for (int c = 0; c < 8; c++) {
                float wr_ = slwr[o*8+c], wi_ = slwi[o*8+c];
                yr = fmaf(wr_, ar[c], yr);
                yr = fmaf(-wi_, ai[c], yr);
                yi = fmaf(wr_, ai[c], yi);
                yi = fmaf(wi_, ar[c], yi);
            }
            sr[o] = yr; si[o] = yi;
        }

        // ---- cMul with x (overwrite sr/si with mr/mi) ----
        #pragma unroll
        for (int c = 0; c < 8; c++) {
            float vxr = xr_p[c*CHW + t];
            float vxi = xi_p[c*CHW + t];
            float mr = sr[c]*vxr - si[c]*vxi;
            float mi = sr[c]*vxi + si[c]*vxr;
            sr[c] = mr; si[c] = mi;
        }

        // ---- last (complex 8x8) -> immediate store ----
        #pragma unroll
        for (int o = 0; o < 8; o++) {
            float yr = sabr[o] - sabi[o];
            float yi = sabr[o] + sabi[o];
            #pragma unroll
            for (int c = 0; c < 8; c++) {
                float wr_ = sawr[o*8+c], wi_ = sawi[o*8+c];
                yr = fmaf(wr_, sr[c], yr);
                yr = fmaf(-wi_, si[c], yr);
                yi = fmaf(wr_, si[c], yi);
                yi = fmaf(wi_, sr[c], yi);
            }
            outr[o*CHW + t] = yr;
            outi[o*CHW + t] = yi;
        }
    }
}

// ---------------------------------------------------------------------------
extern "C" void kernel_launch(void* const* d_in, const int* in_sizes, int n_in,
                              void* d_out, int out_size)
{
    const float* x     = (const float*)d_in[0];
    const float* cs_wr = (const float*)d_in[1];
    const float* cs_wi = (const float*)d_in[2];
    const float* cs_br = (const float*)d_in[3];
    const float* cs_bi = (const float*)d_in[4];
    const float* fc_wr = (const float*)d_in[5];
    const float* fc_wi = (const float*)d_in[6];
    const float* fc_br = (const float*)d_in[7];
    const float* fc_bi = (const float*)d_in[8];
    const float* tc_wr = (const float*)d_in[9];
    const float* tc_wi = (const float*)d_in[10];
    const float* tc_br = (const float*)d_in[11];
    const float* tc_bi = (const float*)d_in[12];
    const float* ls_wr = (const float*)d_in[13];
    const float* ls_wi = (const float*)d_in[14];
    const float* ls_br = (const float*)d_in[15];
    const float* ls_bi = (const float*)d_in[16];
    const float* la_wr = (const float*)d_in[17];
    const float* la_wi = (const float*)d_in[18];
    const float* la_br = (const float*)d_in[19];
    const float* la_bi = (const float*)d_in[20];
    float* out = (float*)d_out;

    dim3 gA((TN/2 + 255)/256, FF, BB);
    kA<<<gA, 256>>>(x, cs_wr, cs_wi, cs_br, cs_bi);

    dim3 gB((TN/2 + 255)/256, FF, BB*C16);
    kB<<<gB, 256>>>(fc_wr, fc_wi, fc_br, fc_bi);

    kC<<<BB*FF, 256>>>(x, tc_wr, tc_wi, tc_br, tc_bi,
                       ls_wr, ls_wi, ls_br, ls_bi,
                       la_wr, la_wi, la_br, la_bi, out);
}

// round 8
// speedup vs baseline: 1.1874x; 1.0543x over previous
#include <cuda_runtime.h>
#include <math.h>

#define BB   4
#define C8   8
#define C16  16
#define FF   256
#define TN   2000
#define CHW  (FF*TN)
#define TWO_PI_F     6.283185307179586f
#define INV_TWO_PI_F 0.15915494309189535f

typedef unsigned long long ull;

__device__ float g_s1[BB*2*C16*CHW];
__device__ float g_s2[BB*2*C16*CHW];

__device__ __forceinline__ float mod2pi(float a) {
    return a - floorf(a * INV_TWO_PI_F) * TWO_PI_F;
}

// ---- f32x2 helpers (kA/kB only) ----
__device__ __forceinline__ ull pk(float lo, float hi) {
    ull r; asm("mov.b64 %0,{%1,%2};" : "=l"(r) : "f"(lo), "f"(hi)); return r;
}
__device__ __forceinline__ void upk(ull v, float& lo, float& hi) {
    asm("mov.b64 {%0,%1},%2;" : "=f"(lo), "=f"(hi) : "l"(v));
}
__device__ __forceinline__ ull ffma2(ull a, ull b, ull c) {
    ull d; asm("fma.rn.f32x2 %0,%1,%2,%3;" : "=l"(d) : "l"(a), "l"(b), "l"(c)); return d;
}
__device__ __forceinline__ ull ld64(const float* p) {
    return *reinterpret_cast<const ull*>(p);
}
__device__ __forceinline__ void st64(float* p, ull v) {
    *reinterpret_cast<ull*>(p) = v;
}

// ---------------------------------------------------------------------------
// Kernel A: cLog -> channel_shuffle (8->16) -> cAct.  2 timesteps per thread.
// (measured 106 us, DRAM-bound-ish)
// ---------------------------------------------------------------------------
__global__ void kA(const float* __restrict__ x,
                   const float* __restrict__ wr, const float* __restrict__ wi,
                   const float* __restrict__ br, const float* __restrict__ bi)
{
    const int f = blockIdx.y;
    const int b = blockIdx.z;

    __shared__ ull swr2[C16*C8], swi2[C16*C8];
    __shared__ ull sbr2[C16], sbi2[C16];
    for (int i = threadIdx.x; i < C16*C8; i += blockDim.x) {
        float a = wr[f*C16*C8 + i]; swr2[i] = pk(a, a);
        float c = wi[f*C16*C8 + i]; swi2[i] = pk(c, c);
    }
    if (threadIdx.x < C16) {
        float a = br[f*C16 + threadIdx.x]; sbr2[threadIdx.x] = pk(a, a);
        float c = bi[f*C16 + threadIdx.x]; sbi2[threadIdx.x] = pk(c, c);
    }
    __syncthreads();

    const int tp = 2 * (blockIdx.x * blockDim.x + threadIdx.x);
    if (tp >= TN) return;
    const int off = f*TN + tp;

    ull lm2[C8], ph2[C8];
    #pragma unroll
    for (int c = 0; c < C8; c++) {
        ull xr = ld64(x + ((b*2+0)*C8 + c)*CHW + off);
        ull xi = ld64(x + ((b*2+1)*C8 + c)*CHW + off);
        float r0, r1, i0, i1;
        upk(xr, r0, r1); upk(xi, i0, i1);
        float l0 = 0.5f * __logf(fmaf(r0, r0, fmaf(i0, i0, 1e-12f)));
        float l1 = 0.5f * __logf(fmaf(r1, r1, fmaf(i1, i1, 1e-12f)));
        lm2[c] = pk(l0, l1);
        ph2[c] = pk(atan2f(i0, r0), atan2f(i1, r1));
    }
    #pragma unroll
    for (int o = 0; o < C16; o++) {
        ull sr = sbr2[o], si = sbi2[o];
        #pragma unroll
        for (int c = 0; c < C8; c++) {
            sr = ffma2(swr2[o*C8+c], lm2[c], sr);
            si = ffma2(swi2[o*C8+c], ph2[c], si);
        }
        float s0, s1, p0, p1;
        upk(sr, s0, s1); upk(si, p0, p1);
        float w0 = (__cosf(p0) + 1.0f) * 0.5f;
        float w1 = (__cosf(p1) + 1.0f) * 0.5f;
        st64(g_s1 + ((b*2+0)*C16 + o)*CHW + off, pk(w0*s0, w1*s1));
        st64(g_s1 + ((b*2+1)*C16 + o)*CHW + off, pk(mod2pi(p0), mod2pi(p1)));
    }
}

// ---------------------------------------------------------------------------
// Kernel B: freq_conv (depthwise over freq, k=5, pad=2) -> cAct. 2 t/thread.
// ---------------------------------------------------------------------------
__global__ void kB(const float* __restrict__ wr, const float* __restrict__ wi,
                   const float* __restrict__ br, const float* __restrict__ bi)
{
    const int f  = blockIdx.y;
    const int bc = blockIdx.z;
    const int b  = bc / C16;
    const int c  = bc % C16;
    const int tp = 2 * (blockIdx.x * blockDim.x + threadIdx.x);
    if (tp >= TN) return;

    const int base_r = ((b*2+0)*C16 + c)*CHW;
    const int base_i = ((b*2+1)*C16 + c)*CHW;

    float b_r = br[c], b_i = bi[c];
    ull yr = pk(b_r, b_r);
    ull yi = pk(b_i, b_i);
    #pragma unroll
    for (int j = 0; j < 5; j++) {
        int ff = f + j - 2;
        if (ff >= 0 && ff < FF) {
            float a = wr[c*5 + j]; float d = wi[c*5 + j];
            yr = ffma2(pk(a, a), ld64(g_s1 + base_r + ff*TN + tp), yr);
            yi = ffma2(pk(d, d), ld64(g_s1 + base_i + ff*TN + tp), yi);
        }
    }
    float r0, r1, i0, i1;
    upk(yr, r0, r1); upk(yi, i0, i1);
    float w0 = (__cosf(i0) + 1.0f) * 0.5f;
    float w1 = (__cosf(i1) + 1.0f) * 0.5f;
    st64(g_s2 + base_r + f*TN + tp, pk(w0*r0, w1*r1));
    st64(g_s2 + base_i + f*TN + tp, pk(mod2pi(i0), mod2pi(i1)));
}

// ---------------------------------------------------------------------------
// Kernel C: R3 structure (2 t/thread, float2 taps, uniform LDS.128 weights)
// but register-capped for 2 blocks/SM: launch_bounds(256,2), immediate
// scalar stores, no cross-iteration pipelining.
// ---------------------------------------------------------------------------
template<bool FULL>
__device__ __forceinline__ void tc_core(
    const float* __restrict__ s2r, const float* __restrict__ s2i,
    const float* __restrict__ stwr, const float* __restrict__ stwi,
    int t0, float ar[8][2], float ai[8][2])
{
    #pragma unroll
    for (int c = 0; c < C16; c++) {
        float vr[10], vi[10];
        if (FULL) {
            #pragma unroll
            for (int m = 0; m < 5; m++) {
                float2 a = *reinterpret_cast<const float2*>(s2r + c*CHW + t0 + 2*m);
                float2 d = *reinterpret_cast<const float2*>(s2i + c*CHW + t0 + 2*m);
                vr[2*m] = a.x; vr[2*m+1] = a.y;
                vi[2*m] = d.x; vi[2*m+1] = d.y;
            }
        } else {
            #pragma unroll
            for (int j = 0; j < 10; j++) {
                int tt = t0 + j;
                vr[j] = (tt < TN) ? s2r[c*CHW + tt] : 0.0f;
                vi[j] = (tt < TN) ? s2i[c*CHW + tt] : 0.0f;
            }
        }
        #pragma unroll
        for (int k = 0; k < 5; k++) {
            const float4 wr0 = *reinterpret_cast<const float4*>(stwr + (c*5+k)*8);
            const float4 wr1 = *reinterpret_cast<const float4*>(stwr + (c*5+k)*8 + 4);
            const float4 wi0 = *reinterpret_cast<const float4*>(stwi + (c*5+k)*8);
            const float4 wi1 = *reinterpret_cast<const float4*>(stwi + (c*5+k)*8 + 4);
            const float wrs[8] = {wr0.x, wr0.y, wr0.z, wr0.w, wr1.x, wr1.y, wr1.z, wr1.w};
            const float wis[8] = {wi0.x, wi0.y, wi0.z, wi0.w, wi1.x, wi1.y, wi1.z, wi1.w};
            #pragma unroll
            for (int o = 0; o < 8; o++) {
                ar[o][0] = fmaf(wrs[o], vr[2*k],   ar[o][0]);
                ar[o][1] = fmaf(wrs[o], vr[2*k+1], ar[o][1]);
                ai[o][0] = fmaf(wis[o], vi[2*k],   ai[o][0]);
                ai[o][1] = fmaf(wis[o], vi[2*k+1], ai[o][1]);
            }
        }
    }
}

__global__ void __launch_bounds__(256, 2) kC(
    const float* __restrict__ x,
    const float* __restrict__ twr, const float* __restrict__ twi,
    const float* __restrict__ tbr, const float* __restrict__ tbi,
    const float* __restrict__ lwr, const float* __restrict__ lwi,
    const float* __restrict__ lbr, const float* __restrict__ lbi,
    const float* __restrict__ awr, const float* __restrict__ awi,
    const float* __restrict__ abr, const float* __restrict__ abi,
    float* __restrict__ out)
{
    const int f = blockIdx.x & (FF-1);
    const int b = blockIdx.x >> 8;

    __shared__ __align__(16) float stwr[C8*C16*5], stwi[C8*C16*5];  // [(c*5+k)*8+o]
    __shared__ float slwr[64], slwi[64], sawr[64], sawi[64];        // [o*8+c]
    __shared__ float stbr[8], stbi[8], slbr[8], slbi[8], sabr[8], sabi[8];

    for (int i = threadIdx.x; i < C8*C16*5; i += blockDim.x) {
        int o = i & 7, ck = i >> 3;
        int c = ck / 5, k = ck - 5*c;
        stwr[i] = twr[f*C8*C16*5 + (o*C16 + c)*5 + k];
        stwi[i] = twi[f*C8*C16*5 + (o*C16 + c)*5 + k];
    }
    if (threadIdx.x < 64) {
        slwr[threadIdx.x] = lwr[f*64 + threadIdx.x];
        slwi[threadIdx.x] = lwi[f*64 + threadIdx.x];
        sawr[threadIdx.x] = awr[f*64 + threadIdx.x];
        sawi[threadIdx.x] = awi[f*64 + threadIdx.x];
    }
    if (threadIdx.x < 8) {
        stbr[threadIdx.x] = tbr[f*8 + threadIdx.x];
        stbi[threadIdx.x] = tbi[f*8 + threadIdx.x];
        slbr[threadIdx.x] = lbr[f*8 + threadIdx.x];
        slbi[threadIdx.x] = lbi[f*8 + threadIdx.x];
        sabr[threadIdx.x] = abr[f*8 + threadIdx.x];
        sabi[threadIdx.x] = abi[f*8 + threadIdx.x];
    }
    __syncthreads();

    const float* s2r  = g_s2 + (b*2+0)*C16*CHW + f*TN;
    const float* s2i  = g_s2 + (b*2+1)*C16*CHW + f*TN;
    const float* xr_p = x    + (b*2+0)*C8 *CHW + f*TN;
    const float* xi_p = x    + (b*2+1)*C8 *CHW + f*TN;
    float* outr = out + (b*2+0)*C8*CHW + f*TN;
    float* outi = out + (b*2+1)*C8*CHW + f*TN;

    #pragma unroll 1
    for (int t0 = 2*threadIdx.x; t0 < TN; t0 += 2*blockDim.x) {
        float ar[8][2], ai[8][2];
        #pragma unroll
        for (int o = 0; o < 8; o++) {
            ar[o][0] = stbr[o]; ar[o][1] = stbr[o];
            ai[o][0] = stbi[o]; ai[o][1] = stbi[o];
        }

        if (t0 + 9 < TN) tc_core<true >(s2r, s2i, stwr, stwi, t0, ar, ai);
        else             tc_core<false>(s2r, s2i, stwr, stwi, t0, ar, ai);

        #pragma unroll
        for (int j = 0; j < 2; j++) {
            // cExp
            float er[8], ei[8];
            #pragma unroll
            for (int o = 0; o < 8; o++) {
                float r = __expf(ar[o][j]);
                float sn, cs;
                __sincosf(ai[o][j], &sn, &cs);
                er[o] = r * cs;
                ei[o] = r * sn;
            }
            // last_shuffle (complex 8x8)
            float sr[8], si[8];
            #pragma unroll
            for (int o = 0; o < 8; o++) {
                float yr = slbr[o] - slbi[o];
                float yi = slbr[o] + slbi[o];
                #pragma unroll
                for (int c = 0; c < 8; c++) {
                    float wr_ = slwr[o*8+c], wi_ = slwi[o*8+c];
                    yr = fmaf(wr_, er[c], yr);
                    yr = fmaf(-wi_, ei[c], yr);
                    yi = fmaf(wr_, ei[c], yi);
                    yi = fmaf(wi_, er[c], yi);
                }
                sr[o] = yr; si[o] = yi;
            }
            // cMul with x (in place)
            #pragma unroll
            for (int c = 0; c < 8; c++) {
                float vxr = xr_p[c*CHW + t0 + j];
                float vxi = xi_p[c*CHW + t0 + j];
                float mr = sr[c]*vxr - si[c]*vxi;
                float mi = sr[c]*vxi + si[c]*vxr;
                sr[c] = mr; si[c] = mi;
            }
            // last (complex 8x8) -> immediate scalar stores
            #pragma unroll
            for (int o = 0; o < 8; o++) {
                float yr = sabr[o] - sabi[o];
                float yi = sabr[o] + sabi[o];
                #pragma unroll
                for (int c = 0; c < 8; c++) {
                    float wr_ = sawr[o*8+c], wi_ = sawi[o*8+c];
                    yr = fmaf(wr_, sr[c], yr);
                    yr = fmaf(-wi_, si[c], yr);
                    yi = fmaf(wr_, si[c], yi);
                    yi = fmaf(wi_, sr[c], yi);
                }
                outr[o*CHW + t0 + j] = yr;
                outi[o*CHW + t0 + j] = yi;
            }
        }
    }
}

// ---------------------------------------------------------------------------
extern "C" void kernel_launch(void* const* d_in, const int* in_sizes, int n_in,
                              void* d_out, int out_size)
{
    const float* x     = (const float*)d_in[0];
    const float* cs_wr = (const float*)d_in[1];
    const float* cs_wi = (const float*)d_in[2];
    const float* cs_br = (const float*)d_in[3];
    const float* cs_bi = (const float*)d_in[4];
    const float* fc_wr = (const float*)d_in[5];
    const float* fc_wi = (const float*)d_in[6];
    const float* fc_br = (const float*)d_in[7];
    const float* fc_bi = (const float*)d_in[8];
    const float* tc_wr = (const float*)d_in[9];
    const float* tc_wi = (const float*)d_in[10];
    const float* tc_br = (const float*)d_in[11];
    const float* tc_bi = (const float*)d_in[12];
    const float* ls_wr = (const float*)d_in[13];
    const float* ls_wi = (const float*)d_in[14];
    const float* ls_br = (const float*)d_in[15];
    const float* ls_bi = (const float*)d_in[16];
    const float* la_wr = (const float*)d_in[17];
    const float* la_wi = (const float*)d_in[18];
    const float* la_br = (const float*)d_in[19];
    const float* la_bi = (const float*)d_in[20];
    float* out = (float*)d_out;

    dim3 gA((TN/2 + 255)/256, FF, BB);
    kA<<<gA, 256>>>(x, cs_wr, cs_wi, cs_br, cs_bi);

    dim3 gB((TN/2 + 255)/256, FF, BB*C16);
    kB<<<gB, 256>>>(fc_wr, fc_wi, fc_br, fc_bi);

    kC<<<BB*FF, 256>>>(x, tc_wr, tc_wi, tc_br, tc_bi,
                       ls_wr, ls_wi, ls_br, ls_bi,
                       la_wr, la_wi, la_br, la_bi, out);
}

// round 9
// speedup vs baseline: 1.3800x; 1.1622x over previous
#include <cuda_runtime.h>
#include <math.h>

#define BB   4
#define C8   8
#define C16  16
#define FF   256
#define TN   2000
#define CHW  (FF*TN)
#define TWO_PI_F     6.283185307179586f
#define INV_TWO_PI_F 0.15915494309189535f

typedef unsigned long long ull;

__device__ float g_s1[BB*2*C16*CHW];
__device__ float g_s2[BB*2*C16*CHW];

__device__ __forceinline__ float mod2pi(float a) {
    return a - floorf(a * INV_TWO_PI_F) * TWO_PI_F;
}

// ---- f32x2 helpers (kA/kB only) ----
__device__ __forceinline__ ull pk(float lo, float hi) {
    ull r; asm("mov.b64 %0,{%1,%2};" : "=l"(r) : "f"(lo), "f"(hi)); return r;
}
__device__ __forceinline__ void upk(ull v, float& lo, float& hi) {
    asm("mov.b64 {%0,%1},%2;" : "=f"(lo), "=f"(hi) : "l"(v));
}
__device__ __forceinline__ ull ffma2(ull a, ull b, ull c) {
    ull d; asm("fma.rn.f32x2 %0,%1,%2,%3;" : "=l"(d) : "l"(a), "l"(b), "l"(c)); return d;
}
__device__ __forceinline__ ull ld64(const float* p) {
    return *reinterpret_cast<const ull*>(p);
}
__device__ __forceinline__ void st64(float* p, ull v) {
    *reinterpret_cast<ull*>(p) = v;
}

// ---------------------------------------------------------------------------
// Kernel A: cLog -> channel_shuffle (8->16) -> cAct.  2 timesteps per thread.
// (measured ~105 us)
// ---------------------------------------------------------------------------
__global__ void kA(const float* __restrict__ x,
                   const float* __restrict__ wr, const float* __restrict__ wi,
                   const float* __restrict__ br, const float* __restrict__ bi)
{
    const int f = blockIdx.y;
    const int b = blockIdx.z;

    __shared__ ull swr2[C16*C8], swi2[C16*C8];
    __shared__ ull sbr2[C16], sbi2[C16];
    for (int i = threadIdx.x; i < C16*C8; i += blockDim.x) {
        float a = wr[f*C16*C8 + i]; swr2[i] = pk(a, a);
        float c = wi[f*C16*C8 + i]; swi2[i] = pk(c, c);
    }
    if (threadIdx.x < C16) {
        float a = br[f*C16 + threadIdx.x]; sbr2[threadIdx.x] = pk(a, a);
        float c = bi[f*C16 + threadIdx.x]; sbi2[threadIdx.x] = pk(c, c);
    }
    __syncthreads();

    const int tp = 2 * (blockIdx.x * blockDim.x + threadIdx.x);
    if (tp >= TN) return;
    const int off = f*TN + tp;

    ull lm2[C8], ph2[C8];
    #pragma unroll
    for (int c = 0; c < C8; c++) {
        ull xr = ld64(x + ((b*2+0)*C8 + c)*CHW + off);
        ull xi = ld64(x + ((b*2+1)*C8 + c)*CHW + off);
        float r0, r1, i0, i1;
        upk(xr, r0, r1); upk(xi, i0, i1);
        float l0 = 0.5f * __logf(fmaf(r0, r0, fmaf(i0, i0, 1e-12f)));
        float l1 = 0.5f * __logf(fmaf(r1, r1, fmaf(i1, i1, 1e-12f)));
        lm2[c] = pk(l0, l1);
        ph2[c] = pk(atan2f(i0, r0), atan2f(i1, r1));
    }
    #pragma unroll
    for (int o = 0; o < C16; o++) {
        ull sr = sbr2[o], si = sbi2[o];
        #pragma unroll
        for (int c = 0; c < C8; c++) {
            sr = ffma2(swr2[o*C8+c], lm2[c], sr);
            si = ffma2(swi2[o*C8+c], ph2[c], si);
        }
        float s0, s1, p0, p1;
        upk(sr, s0, s1); upk(si, p0, p1);
        float w0 = (__cosf(p0) + 1.0f) * 0.5f;
        float w1 = (__cosf(p1) + 1.0f) * 0.5f;
        st64(g_s1 + ((b*2+0)*C16 + o)*CHW + off, pk(w0*s0, w1*s1));
        st64(g_s1 + ((b*2+1)*C16 + o)*CHW + off, pk(mod2pi(p0), mod2pi(p1)));
    }
}

// ---------------------------------------------------------------------------
// Kernel B: freq_conv (depthwise over freq, k=5, pad=2) -> cAct. 2 t/thread.
// ---------------------------------------------------------------------------
__global__ void kB(const float* __restrict__ wr, const float* __restrict__ wi,
                   const float* __restrict__ br, const float* __restrict__ bi)
{
    const int f  = blockIdx.y;
    const int bc = blockIdx.z;
    const int b  = bc / C16;
    const int c  = bc % C16;
    const int tp = 2 * (blockIdx.x * blockDim.x + threadIdx.x);
    if (tp >= TN) return;

    const int base_r = ((b*2+0)*C16 + c)*CHW;
    const int base_i = ((b*2+1)*C16 + c)*CHW;

    float b_r = br[c], b_i = bi[c];
    ull yr = pk(b_r, b_r);
    ull yi = pk(b_i, b_i);
    #pragma unroll
    for (int j = 0; j < 5; j++) {
        int ff = f + j - 2;
        if (ff >= 0 && ff < FF) {
            float a = wr[c*5 + j]; float d = wi[c*5 + j];
            yr = ffma2(pk(a, a), ld64(g_s1 + base_r + ff*TN + tp), yr);
            yi = ffma2(pk(d, d), ld64(g_s1 + base_i + ff*TN + tp), yi);
        }
    }
    float r0, r1, i0, i1;
    upk(yr, r0, r1); upk(yi, i0, i1);
    float w0 = (__cosf(i0) + 1.0f) * 0.5f;
    float w1 = (__cosf(i1) + 1.0f) * 0.5f;
    st64(g_s2 + base_r + f*TN + tp, pk(w0*r0, w1*r1));
    st64(g_s2 + base_i + f*TN + tp, pk(mod2pi(i0), mod2pi(i1)));
}

// ---------------------------------------------------------------------------
// Kernel C: R3 structure (2 t/thread, float2 taps, uniform LDS.128 weights,
// buffered float2 stores), 128-thread blocks, launch_bounds(128,3) -> 170-reg
// cap (no spills, 3 warps/SMSP).  Grid split in t for finer waves.
// ---------------------------------------------------------------------------
#define KC_THREADS 128
#define KC_TSPLIT  2
#define KC_TLEN    (TN / KC_TSPLIT)      // 1000

template<bool FULL>
__device__ __forceinline__ void tc_core(
    const float* __restrict__ s2r, const float* __restrict__ s2i,
    const float* __restrict__ stwr, const float* __restrict__ stwi,
    int t0, float ar[8][2], float ai[8][2])
{
    #pragma unroll
    for (int c = 0; c < C16; c++) {
        float vr[10], vi[10];
        if (FULL) {
            #pragma unroll
            for (int m = 0; m < 5; m++) {
                float2 a = *reinterpret_cast<const float2*>(s2r + c*CHW + t0 + 2*m);
                float2 d = *reinterpret_cast<const float2*>(s2i + c*CHW + t0 + 2*m);
                vr[2*m] = a.x; vr[2*m+1] = a.y;
                vi[2*m] = d.x; vi[2*m+1] = d.y;
            }
        } else {
            #pragma unroll
            for (int j = 0; j < 10; j++) {
                int tt = t0 + j;
                vr[j] = (tt < TN) ? s2r[c*CHW + tt] : 0.0f;
                vi[j] = (tt < TN) ? s2i[c*CHW + tt] : 0.0f;
            }
        }
        #pragma unroll
        for (int k = 0; k < 5; k++) {
            const float4 wr0 = *reinterpret_cast<const float4*>(stwr + (c*5+k)*8);
            const float4 wr1 = *reinterpret_cast<const float4*>(stwr + (c*5+k)*8 + 4);
            const float4 wi0 = *reinterpret_cast<const float4*>(stwi + (c*5+k)*8);
            const float4 wi1 = *reinterpret_cast<const float4*>(stwi + (c*5+k)*8 + 4);
            const float wrs[8] = {wr0.x, wr0.y, wr0.z, wr0.w, wr1.x, wr1.y, wr1.z, wr1.w};
            const float wis[8] = {wi0.x, wi0.y, wi0.z, wi0.w, wi1.x, wi1.y, wi1.z, wi1.w};
            #pragma unroll
            for (int o = 0; o < 8; o++) {
                ar[o][0] = fmaf(wrs[o], vr[2*k],   ar[o][0]);
                ar[o][1] = fmaf(wrs[o], vr[2*k+1], ar[o][1]);
                ai[o][0] = fmaf(wis[o], vi[2*k],   ai[o][0]);
                ai[o][1] = fmaf(wis[o], vi[2*k+1], ai[o][1]);
            }
        }
    }
}

__global__ void __launch_bounds__(KC_THREADS, 3) kC(
    const float* __restrict__ x,
    const float* __restrict__ twr, const float* __restrict__ twi,
    const float* __restrict__ tbr, const float* __restrict__ tbi,
    const float* __restrict__ lwr, const float* __restrict__ lwi,
    const float* __restrict__ lbr, const float* __restrict__ lbi,
    const float* __restrict__ awr, const float* __restrict__ awi,
    const float* __restrict__ abr, const float* __restrict__ abi,
    float* __restrict__ out)
{
    const int f    = blockIdx.x & (FF-1);
    const int bh   = blockIdx.x >> 8;
    const int b    = bh >> 1;               // batch
    const int half = bh & 1;                // t-range half
    const int tBeg = half * KC_TLEN;
    const int tEnd = tBeg + KC_TLEN;

    __shared__ __align__(16) float stwr[C8*C16*5], stwi[C8*C16*5];  // [(c*5+k)*8+o]
    __shared__ float slwr[64], slwi[64], sawr[64], sawi[64];        // [o*8+c]
    __shared__ float stbr[8], stbi[8], slbr[8], slbi[8], sabr[8], sabi[8];

    for (int i = threadIdx.x; i < C8*C16*5; i += KC_THREADS) {
        int o = i & 7, ck = i >> 3;
        int c = ck / 5, k = ck - 5*c;
        stwr[i] = twr[f*C8*C16*5 + (o*C16 + c)*5 + k];
        stwi[i] = twi[f*C8*C16*5 + (o*C16 + c)*5 + k];
    }
    if (threadIdx.x < 64) {
        slwr[threadIdx.x] = lwr[f*64 + threadIdx.x];
        slwi[threadIdx.x] = lwi[f*64 + threadIdx.x];
        sawr[threadIdx.x] = awr[f*64 + threadIdx.x];
        sawi[threadIdx.x] = awi[f*64 + threadIdx.x];
    }
    if (threadIdx.x < 8) {
        stbr[threadIdx.x] = tbr[f*8 + threadIdx.x];
        stbi[threadIdx.x] = tbi[f*8 + threadIdx.x];
        slbr[threadIdx.x] = lbr[f*8 + threadIdx.x];
        slbi[threadIdx.x] = lbi[f*8 + threadIdx.x];
        sabr[threadIdx.x] = abr[f*8 + threadIdx.x];
        sabi[threadIdx.x] = abi[f*8 + threadIdx.x];
    }
    __syncthreads();

    const float* s2r  = g_s2 + (b*2+0)*C16*CHW + f*TN;
    const float* s2i  = g_s2 + (b*2+1)*C16*CHW + f*TN;
    const float* xr_p = x    + (b*2+0)*C8 *CHW + f*TN;
    const float* xi_p = x    + (b*2+1)*C8 *CHW + f*TN;
    float* outr = out + (b*2+0)*C8*CHW + f*TN;
    float* outi = out + (b*2+1)*C8*CHW + f*TN;

    for (int t0 = tBeg + 2*threadIdx.x; t0 < tEnd; t0 += 2*KC_THREADS) {
        float ar[8][2], ai[8][2];
        #pragma unroll
        for (int o = 0; o < 8; o++) {
            ar[o][0] = stbr[o]; ar[o][1] = stbr[o];
            ai[o][0] = stbi[o]; ai[o][1] = stbi[o];
        }

        if (t0 + 9 < TN) tc_core<true >(s2r, s2i, stwr, stwi, t0, ar, ai);
        else             tc_core<false>(s2r, s2i, stwr, stwi, t0, ar, ai);

        float orj[8][2], oij[8][2];
        #pragma unroll
        for (int j = 0; j < 2; j++) {
            // cExp
            float er[8], ei[8];
            #pragma unroll
            for (int o = 0; o < 8; o++) {
                float r = __expf(ar[o][j]);
                float sn, cs;
                __sincosf(ai[o][j], &sn, &cs);
                er[o] = r * cs;
                ei[o] = r * sn;
            }
            // last_shuffle (complex 8x8)
            float sr[8], si[8];
            #pragma unroll
            for (int o = 0; o < 8; o++) {
                float yr = slbr[o] - slbi[o];
                float yi = slbr[o] + slbi[o];
                #pragma unroll
                for (int c = 0; c < 8; c++) {
                    float wr_ = slwr[o*8+c], wi_ = slwi[o*8+c];
                    yr = fmaf(wr_, er[c], yr);
                    yr = fmaf(-wi_, ei[c], yr);
                    yi = fmaf(wr_, ei[c], yi);
                    yi = fmaf(wi_, er[c], yi);
                }
                sr[o] = yr; si[o] = yi;
            }
            // cMul with x (in place)
            #pragma unroll
            for (int c = 0; c < 8; c++) {
                float vxr = xr_p[c*CHW + t0 + j];
                float vxi = xi_p[c*CHW + t0 + j];
                float mr = sr[c]*vxr - si[c]*vxi;
                float mi = sr[c]*vxi + si[c]*vxr;
                sr[c] = mr; si[c] = mi;
            }
            // last (complex 8x8)
            #pragma unroll
            for (int o = 0; o < 8; o++) {
                float yr = sabr[o] - sabi[o];
                float yi = sabr[o] + sabi[o];
                #pragma unroll
                for (int c = 0; c < 8; c++) {
                    float wr_ = sawr[o*8+c], wi_ = sawi[o*8+c];
                    yr = fmaf(wr_, sr[c], yr);
                    yr = fmaf(-wi_, si[c], yr);
                    yi = fmaf(wr_, si[c], yi);
                    yi = fmaf(wi_, sr[c], yi);
                }
                orj[o][j] = yr; oij[o][j] = yi;
            }
        }
        #pragma unroll
        for (int o = 0; o < 8; o++) {
            *reinterpret_cast<float2*>(outr + o*CHW + t0) = make_float2(orj[o][0], orj[o][1]);
            *reinterpret_cast<float2*>(outi + o*CHW + t0) = make_float2(oij[o][0], oij[o][1]);
        }
    }
}

// ---------------------------------------------------------------------------
extern "C" void kernel_launch(void* const* d_in, const int* in_sizes, int n_in,
                              void* d_out, int out_size)
{
    const float* x     = (const float*)d_in[0];
    const float* cs_wr = (const float*)d_in[1];
    const float* cs_wi = (const float*)d_in[2];
    const float* cs_br = (const float*)d_in[3];
    const float* cs_bi = (const float*)d_in[4];
    const float* fc_wr = (const float*)d_in[5];
    const float* fc_wi = (const float*)d_in[6];
    const float* fc_br = (const float*)d_in[7];
    const float* fc_bi = (const float*)d_in[8];
    const float* tc_wr = (const float*)d_in[9];
    const float* tc_wi = (const float*)d_in[10];
    const float* tc_br = (const float*)d_in[11];
    const float* tc_bi = (const float*)d_in[12];
    const float* ls_wr = (const float*)d_in[13];
    const float* ls_wi = (const float*)d_in[14];
    const float* ls_br = (const float*)d_in[15];
    const float* ls_bi = (const float*)d_in[16];
    const float* la_wr = (const float*)d_in[17];
    const float* la_wi = (const float*)d_in[18];
    const float* la_br = (const float*)d_in[19];
    const float* la_bi = (const float*)d_in[20];
    float* out = (float*)d_out;

    dim3 gA((TN/2 + 255)/256, FF, BB);
    kA<<<gA, 256>>>(x, cs_wr, cs_wi, cs_br, cs_bi);

    dim3 gB((TN/2 + 255)/256, FF, BB*C16);
    kB<<<gB, 256>>>(fc_wr, fc_wi, fc_br, fc_bi);

    kC<<<BB*KC_TSPLIT*FF, KC_THREADS>>>(x, tc_wr, tc_wi, tc_br, tc_bi,
                                        ls_wr, ls_wi, ls_br, ls_bi,
                                        la_wr, la_wi, la_br, la_bi, out);
}